// round 2
// baseline (speedup 1.0000x reference)
#include <cuda_runtime.h>
#include <cuda_bf16.h>
#include <stdint.h>

#define N_NODES 50000
#define E_EDGES 800000
#define IN_C    10
#define HID     96
#define OUT_C   48

// ---- scratch (device globals; no allocation allowed) ----
__device__ float g_deg [N_NODES];
__device__ float g_dis [N_NODES];
__device__ float g_aggx[N_NODES * IN_C];
__device__ float g_h   [N_NODES * HID];
__device__ float g_aggh[N_NODES * HID];

// deg = 1 (self-loop)
__global__ void k_init_deg() {
    int n = blockIdx.x * blockDim.x + threadIdx.x;
    if (n < N_NODES) g_deg[n] = 1.0f;
}

// deg[col] += 1 per edge  (edge_index is int32: JAX downgrades int64 w/o x64)
__global__ void k_degree(const int* __restrict__ ei) {
    int e = blockIdx.x * blockDim.x + threadIdx.x;
    if (e < E_EDGES) {
        int col = __ldg(&ei[E_EDGES + e]);
        atomicAdd(&g_deg[col], 1.0f);
    }
}

// dis = rsqrt(deg)
__global__ void k_dis() {
    int n = blockIdx.x * blockDim.x + threadIdx.x;
    if (n < N_NODES) g_dis[n] = rsqrtf(g_deg[n]);
}

// agg_x init with self-loop term: x[n]*dis[n]^2
__global__ void k_aggx_init(const float* __restrict__ x) {
    int t = blockIdx.x * blockDim.x + threadIdx.x;
    if (t < N_NODES * IN_C) {
        int n = t / IN_C;
        float d = g_dis[n];
        g_aggx[t] = x[t] * d * d;
    }
}

// agg_x[col] += x[row] * dis[row]*dis[col]   (10-wide)
__global__ void k_aggx_edge(const float* __restrict__ x,
                            const int* __restrict__ ei) {
    int e = blockIdx.x * blockDim.x + threadIdx.x;
    if (e >= E_EDGES) return;
    int row = __ldg(&ei[e]);
    int col = __ldg(&ei[E_EDGES + e]);
    float w = __ldg(&g_dis[row]) * __ldg(&g_dis[col]);
    const float* xr = x + (size_t)row * IN_C;
    float* ax = g_aggx + (size_t)col * IN_C;
    #pragma unroll
    for (int c = 0; c < IN_C; c++)
        atomicAdd(&ax[c], __ldg(&xr[c]) * w);
}

// h = relu(agg_x @ W1 + b1) ; block = (HID, 4) -> 4 nodes/block
__global__ void k_layer1(const float* __restrict__ W1,
                         const float* __restrict__ b1) {
    __shared__ float sx[4][IN_C];
    int n = blockIdx.x * 4 + threadIdx.y;
    int j = threadIdx.x;
    if (n < N_NODES && j < IN_C)
        sx[threadIdx.y][j] = g_aggx[(size_t)n * IN_C + j];
    __syncthreads();
    if (n >= N_NODES) return;
    float acc = __ldg(&b1[j]);
    #pragma unroll
    for (int c = 0; c < IN_C; c++)
        acc += sx[threadIdx.y][c] * __ldg(&W1[c * HID + j]);
    g_h[(size_t)n * HID + j] = fmaxf(acc, 0.0f);
}

// agg_h init with self-loop: h[n]*dis[n]^2
__global__ void k_aggh_init() {
    int t = blockIdx.x * blockDim.x + threadIdx.x;
    if (t < N_NODES * HID) {
        int n = t / HID;
        float d = g_dis[n];
        g_aggh[t] = g_h[t] * d * d;
    }
}

// agg_h[col] += h[row] * dis[row]*dis[col]   (96-wide, heavy pass)
// block = (HID, 4) -> 4 edges/block
__global__ void k_aggh_edge(const int* __restrict__ ei) {
    __shared__ int   srow[4];
    __shared__ int   scol[4];
    __shared__ float sw[4];
    int e = blockIdx.x * 4 + threadIdx.y;
    if (threadIdx.x == 0) {
        if (e < E_EDGES) {
            int row = __ldg(&ei[e]);
            int col = __ldg(&ei[E_EDGES + e]);
            srow[threadIdx.y] = row;
            scol[threadIdx.y] = col;
            sw[threadIdx.y] = __ldg(&g_dis[row]) * __ldg(&g_dis[col]);
        } else {
            srow[threadIdx.y] = -1;
        }
    }
    __syncthreads();
    int row = srow[threadIdx.y];
    if (row < 0) return;
    int col = scol[threadIdx.y];
    float w = sw[threadIdx.y];
    int j = threadIdx.x;
    float v = __ldg(&g_h[(size_t)row * HID + j]) * w;
    atomicAdd(&g_aggh[(size_t)col * HID + j], v);
}

// mu = agg_h @ W_mu + b_mu ; logstd = agg_h @ W_logstd + b_logstd
// block = (HID, 4): threads j<48 do mu[j], j>=48 do logstd[j-48]
__global__ void k_out(const float* __restrict__ Wmu,
                      const float* __restrict__ bmu,
                      const float* __restrict__ Wls,
                      const float* __restrict__ bls,
                      float* __restrict__ out) {
    __shared__ float sh[4][HID];
    int n = blockIdx.x * 4 + threadIdx.y;
    int j = threadIdx.x;
    if (n < N_NODES)
        sh[threadIdx.y][j] = g_aggh[(size_t)n * HID + j];
    __syncthreads();
    if (n >= N_NODES) return;
    if (j < OUT_C) {
        float acc = __ldg(&bmu[j]);
        #pragma unroll 8
        for (int c = 0; c < HID; c++)
            acc += sh[threadIdx.y][c] * __ldg(&Wmu[c * OUT_C + j]);
        out[(size_t)n * OUT_C + j] = acc;
    } else {
        int jj = j - OUT_C;
        float acc = __ldg(&bls[jj]);
        #pragma unroll 8
        for (int c = 0; c < HID; c++)
            acc += sh[threadIdx.y][c] * __ldg(&Wls[c * OUT_C + jj]);
        out[(size_t)N_NODES * OUT_C + (size_t)n * OUT_C + jj] = acc;
    }
}

extern "C" void kernel_launch(void* const* d_in, const int* in_sizes, int n_in,
                              void* d_out, int out_size) {
    const float* x   = (const float*)d_in[0];
    const int*   ei  = (const int*)d_in[1];
    const float* W1  = (const float*)d_in[2];
    const float* b1  = (const float*)d_in[3];
    const float* Wmu = (const float*)d_in[4];
    const float* bmu = (const float*)d_in[5];
    const float* Wls = (const float*)d_in[6];
    const float* bls = (const float*)d_in[7];
    float* out = (float*)d_out;

    k_init_deg<<<(N_NODES + 255) / 256, 256>>>();
    k_degree<<<(E_EDGES + 255) / 256, 256>>>(ei);
    k_dis<<<(N_NODES + 255) / 256, 256>>>();
    k_aggx_init<<<(N_NODES * IN_C + 255) / 256, 256>>>(x);
    k_aggx_edge<<<(E_EDGES + 255) / 256, 256>>>(x, ei);
    k_layer1<<<(N_NODES + 3) / 4, dim3(HID, 4)>>>(W1, b1);
    k_aggh_init<<<(N_NODES * HID + 255) / 256, 256>>>();
    k_aggh_edge<<<(E_EDGES + 3) / 4, dim3(HID, 4)>>>(ei);
    k_out<<<(N_NODES + 3) / 4, dim3(HID, 4)>>>(Wmu, bmu, Wls, bls, out);
}

// round 3
// speedup vs baseline: 1.3885x; 1.3885x over previous
#include <cuda_runtime.h>
#include <cuda_bf16.h>
#include <stdint.h>

#define N_NODES 50000
#define E_EDGES 800000
#define IN_C    10
#define HID     96
#define OUT_C   48

// ---- scratch (device globals; no allocation allowed) ----
__device__ int       g_cnt[N_NODES];          // in-degree (excl. self-loop)
__device__ int       g_off[N_NODES + 1];      // CSR offsets by dst
__device__ int       g_cur[N_NODES];          // scatter cursors
__device__ float     g_dis[N_NODES];          // rsqrt(deg+1)
__device__ long long g_edge[E_EDGES];         // packed (w<<32 | src)
__device__ float     g_aggx[N_NODES * IN_C];
__device__ float     g_h   [N_NODES * HID];
__device__ float     g_aggh[N_NODES * HID];

// cnt = 0
__global__ void k_zero_cnt() {
    int n = blockIdx.x * blockDim.x + threadIdx.x;
    if (n < N_NODES) g_cnt[n] = 0;
}

// cnt[col]++ per edge (int32 edge_index)
__global__ void k_count(const int* __restrict__ ei) {
    int e = blockIdx.x * blockDim.x + threadIdx.x;
    if (e < E_EDGES) atomicAdd(&g_cnt[__ldg(&ei[E_EDGES + e])], 1);
}

// single-block exclusive scan over 50k counters; also dis + cursors
__global__ void k_scan() {
    __shared__ int part[1024];
    const int CH = (N_NODES + 1023) / 1024;   // 49
    int tid = threadIdx.x;
    int base = tid * CH;
    int s = 0;
    for (int i = 0; i < CH; i++) {
        int n = base + i;
        if (n < N_NODES) s += g_cnt[n];
    }
    part[tid] = s;
    __syncthreads();
    int val = s;
    for (int o = 1; o < 1024; o <<= 1) {
        int t = (tid >= o) ? part[tid - o] : 0;
        __syncthreads();
        part[tid] += t;
        __syncthreads();
    }
    int run = part[tid] - val;                // exclusive prefix
    for (int i = 0; i < CH; i++) {
        int n = base + i;
        if (n < N_NODES) {
            int c = g_cnt[n];
            g_off[n] = run;
            g_cur[n] = run;
            g_dis[n] = rsqrtf((float)(c + 1));
            run += c;
        }
    }
    if (tid == 1023) g_off[N_NODES] = run;    // == E_EDGES
}

// scatter (src, weight) packed into CSR slots
__global__ void k_fill(const int* __restrict__ ei) {
    int e = blockIdx.x * blockDim.x + threadIdx.x;
    if (e >= E_EDGES) return;
    int row = __ldg(&ei[e]);
    int col = __ldg(&ei[E_EDGES + e]);
    float w = __ldg(&g_dis[row]) * __ldg(&g_dis[col]);
    int pos = atomicAdd(&g_cur[col], 1);
    long long p = ((long long)__float_as_int(w) << 32) | (unsigned int)row;
    g_edge[pos] = p;
}

// agg_x[n][c] = x[n][c]*dis[n]^2 + sum_e x[src][c]*w   (10-wide, CSR)
__global__ void k_aggx_csr(const float* __restrict__ x) {
    int t = blockIdx.x * blockDim.x + threadIdx.x;
    if (t >= N_NODES * IN_C) return;
    int n = t / IN_C, c = t % IN_C;
    float d = g_dis[n];
    float acc = __ldg(&x[t]) * d * d;
    int s = g_off[n], e = g_off[n + 1];
    int i = s;
    for (; i + 1 < e; i += 2) {
        long long p0 = __ldg(&g_edge[i]);
        long long p1 = __ldg(&g_edge[i + 1]);
        acc += __ldg(&x[(size_t)(int)p0 * IN_C + c]) * __int_as_float((int)(p0 >> 32));
        acc += __ldg(&x[(size_t)(int)p1 * IN_C + c]) * __int_as_float((int)(p1 >> 32));
    }
    if (i < e) {
        long long p0 = __ldg(&g_edge[i]);
        acc += __ldg(&x[(size_t)(int)p0 * IN_C + c]) * __int_as_float((int)(p0 >> 32));
    }
    g_aggx[t] = acc;
}

// h = relu(agg_x @ W1 + b1) ; block = (HID, 4)
__global__ void k_layer1(const float* __restrict__ W1,
                         const float* __restrict__ b1) {
    __shared__ float sx[4][IN_C];
    int n = blockIdx.x * 4 + threadIdx.y;
    int j = threadIdx.x;
    if (n < N_NODES && j < IN_C)
        sx[threadIdx.y][j] = g_aggx[(size_t)n * IN_C + j];
    __syncthreads();
    if (n >= N_NODES) return;
    float acc = __ldg(&b1[j]);
    #pragma unroll
    for (int c = 0; c < IN_C; c++)
        acc += sx[threadIdx.y][c] * __ldg(&W1[c * HID + j]);
    g_h[(size_t)n * HID + j] = fmaxf(acc, 0.0f);
}

// agg_h[n][j] = h[n][j]*dis[n]^2 + sum_e h[src][j]*w  (96-wide, CSR)
// block = (96, 4): one node per warp-group of 3 warps; edge meta warp-uniform
__global__ void k_aggh_csr() {
    int n = blockIdx.x * 4 + threadIdx.y;
    if (n >= N_NODES) return;
    int j = threadIdx.x;
    float d = g_dis[n];
    float acc = g_h[(size_t)n * HID + j] * d * d;
    int s = g_off[n], e = g_off[n + 1];
    int i = s;
    for (; i + 1 < e; i += 2) {
        long long p0 = __ldg(&g_edge[i]);
        long long p1 = __ldg(&g_edge[i + 1]);
        int   s0 = (int)p0,                    s1 = (int)p1;
        float w0 = __int_as_float((int)(p0 >> 32));
        float w1 = __int_as_float((int)(p1 >> 32));
        float v0 = __ldg(&g_h[(size_t)s0 * HID + j]);
        float v1 = __ldg(&g_h[(size_t)s1 * HID + j]);
        acc += v0 * w0;
        acc += v1 * w1;
    }
    if (i < e) {
        long long p0 = __ldg(&g_edge[i]);
        acc += __ldg(&g_h[(size_t)(int)p0 * HID + j]) * __int_as_float((int)(p0 >> 32));
    }
    g_aggh[(size_t)n * HID + j] = acc;
}

// mu / logstd projections ; block = (HID, 4)
__global__ void k_out(const float* __restrict__ Wmu,
                      const float* __restrict__ bmu,
                      const float* __restrict__ Wls,
                      const float* __restrict__ bls,
                      float* __restrict__ out) {
    __shared__ float sh[4][HID];
    int n = blockIdx.x * 4 + threadIdx.y;
    int j = threadIdx.x;
    if (n < N_NODES)
        sh[threadIdx.y][j] = g_aggh[(size_t)n * HID + j];
    __syncthreads();
    if (n >= N_NODES) return;
    if (j < OUT_C) {
        float acc = __ldg(&bmu[j]);
        #pragma unroll 8
        for (int c = 0; c < HID; c++)
            acc += sh[threadIdx.y][c] * __ldg(&Wmu[c * OUT_C + j]);
        out[(size_t)n * OUT_C + j] = acc;
    } else {
        int jj = j - OUT_C;
        float acc = __ldg(&bls[jj]);
        #pragma unroll 8
        for (int c = 0; c < HID; c++)
            acc += sh[threadIdx.y][c] * __ldg(&Wls[c * OUT_C + jj]);
        out[(size_t)N_NODES * OUT_C + (size_t)n * OUT_C + jj] = acc;
    }
}

extern "C" void kernel_launch(void* const* d_in, const int* in_sizes, int n_in,
                              void* d_out, int out_size) {
    const float* x   = (const float*)d_in[0];
    const int*   ei  = (const int*)d_in[1];
    const float* W1  = (const float*)d_in[2];
    const float* b1  = (const float*)d_in[3];
    const float* Wmu = (const float*)d_in[4];
    const float* bmu = (const float*)d_in[5];
    const float* Wls = (const float*)d_in[6];
    const float* bls = (const float*)d_in[7];
    float* out = (float*)d_out;

    k_zero_cnt<<<(N_NODES + 255) / 256, 256>>>();
    k_count<<<(E_EDGES + 255) / 256, 256>>>(ei);
    k_scan<<<1, 1024>>>();
    k_fill<<<(E_EDGES + 255) / 256, 256>>>(ei);
    k_aggx_csr<<<(N_NODES * IN_C + 255) / 256, 256>>>(x);
    k_layer1<<<(N_NODES + 3) / 4, dim3(HID, 4)>>>(W1, b1);
    k_aggh_csr<<<(N_NODES + 3) / 4, dim3(HID, 4)>>>();
    k_out<<<(N_NODES + 3) / 4, dim3(HID, 4)>>>(Wmu, bmu, Wls, bls, out);
}

// round 5
// speedup vs baseline: 1.6476x; 1.1866x over previous
#include <cuda_runtime.h>
#include <cuda_bf16.h>
#include <stdint.h>

#define N_NODES 50000
#define E_EDGES 800000
#define IN_C    10
#define HID     96
#define OUT_C   48

// ---- scratch (device globals; no allocation allowed) ----
__device__ int       g_cnt[N_NODES];
__device__ int       g_off[N_NODES + 1];
__device__ int       g_cur[N_NODES];
__device__ float     g_dis[N_NODES];
__device__ long long g_edge[E_EDGES];       // packed (w<<32 | src)
__device__ float     g_h   [N_NODES * HID];
__device__ float     g_aggh[N_NODES * HID];

__global__ void k_zero_cnt() {
    int n = blockIdx.x * blockDim.x + threadIdx.x;
    if (n < N_NODES) g_cnt[n] = 0;
}

__global__ void k_count(const int* __restrict__ ei) {
    int e = blockIdx.x * blockDim.x + threadIdx.x;
    if (e < E_EDGES) atomicAdd(&g_cnt[__ldg(&ei[E_EDGES + e])], 1);
}

// single-block exclusive scan; also dis + cursors
__global__ void k_scan() {
    __shared__ int part[1024];
    const int CH = (N_NODES + 1023) / 1024;   // 49
    int tid = threadIdx.x;
    int base = tid * CH;
    int s = 0;
    for (int i = 0; i < CH; i++) {
        int n = base + i;
        if (n < N_NODES) s += g_cnt[n];
    }
    part[tid] = s;
    __syncthreads();
    int val = s;
    for (int o = 1; o < 1024; o <<= 1) {
        int t = (tid >= o) ? part[tid - o] : 0;
        __syncthreads();
        part[tid] += t;
        __syncthreads();
    }
    int run = part[tid] - val;
    for (int i = 0; i < CH; i++) {
        int n = base + i;
        if (n < N_NODES) {
            int c = g_cnt[n];
            g_off[n] = run;
            g_cur[n] = run;
            g_dis[n] = rsqrtf((float)(c + 1));
            run += c;
        }
    }
    if (tid == 1023) g_off[N_NODES] = run;
}

__global__ void k_fill(const int* __restrict__ ei) {
    int e = blockIdx.x * blockDim.x + threadIdx.x;
    if (e >= E_EDGES) return;
    int row = __ldg(&ei[e]);
    int col = __ldg(&ei[E_EDGES + e]);
    float w = __ldg(&g_dis[row]) * __ldg(&g_dis[col]);
    int pos = atomicAdd(&g_cur[col], 1);
    g_edge[pos] = ((long long)__float_as_int(w) << 32) | (unsigned int)row;
}

// Fused: agg_x (CSR gather, 10-wide) + layer1 projection + relu.
// block = (96, 4): ty = node within block; stage1 uses 9 groups x 10 channels.
__global__ void k_fused1(const float* __restrict__ x,
                         const float* __restrict__ W1,
                         const float* __restrict__ b1) {
    __shared__ float part[4][9][10];
    __shared__ float sagg[4][10];
    __shared__ float sW1[IN_C * HID];   // 3840 B
    __shared__ float sb1[HID];
    int tx = threadIdx.x, ty = threadIdx.y;
    int tid = ty * 96 + tx;
    for (int t = tid; t < IN_C * HID; t += 384) sW1[t] = W1[t];
    if (tid < HID) sb1[tid] = b1[tid];
    int n = blockIdx.x * 4 + ty;

    // stage 1: strided edge reduce, 9 groups of 10 lanes
    int g = tx / 10;
    int c = tx - g * 10;
    if (tx < 90 && n < N_NODES) {
        float p = 0.0f;
        int s = g_off[n], e = g_off[n + 1];
        for (int i = s + g; i < e; i += 9) {
            long long pk = __ldg(&g_edge[i]);
            p += __ldg(&x[(size_t)(int)pk * IN_C + c]) *
                 __int_as_float((int)(pk >> 32));
        }
        part[ty][g][c] = p;
    }
    __syncthreads();
    if (tx < IN_C && n < N_NODES) {
        float d = g_dis[n];
        float a = __ldg(&x[(size_t)n * IN_C + tx]) * d * d;
        #pragma unroll
        for (int g2 = 0; g2 < 9; g2++) a += part[ty][g2][tx];
        sagg[ty][tx] = a;
    }
    __syncthreads();
    if (n >= N_NODES) return;
    float acc = sb1[tx];
    #pragma unroll
    for (int cc = 0; cc < IN_C; cc++)
        acc += sagg[ty][cc] * sW1[cc * HID + tx];
    g_h[(size_t)n * HID + tx] = fmaxf(acc, 0.0f);
}

// agg_h[n][j] = h[n][j]*dis[n]^2 + sum_e h[src][j]*w  (96-wide, unroll 4)
__global__ void k_aggh_csr() {
    int n = blockIdx.x * 4 + threadIdx.y;
    if (n >= N_NODES) return;
    int j = threadIdx.x;
    float d = g_dis[n];
    float acc = g_h[(size_t)n * HID + j] * d * d;
    int s = g_off[n], e = g_off[n + 1];
    int cnt4 = (e - s) & ~3;
    int i = s;
    for (; i < s + cnt4; i += 4) {
        long long p0 = __ldg(&g_edge[i]);
        long long p1 = __ldg(&g_edge[i + 1]);
        long long p2 = __ldg(&g_edge[i + 2]);
        long long p3 = __ldg(&g_edge[i + 3]);
        float v0 = __ldg(&g_h[(size_t)(int)p0 * HID + j]);
        float v1 = __ldg(&g_h[(size_t)(int)p1 * HID + j]);
        float v2 = __ldg(&g_h[(size_t)(int)p2 * HID + j]);
        float v3 = __ldg(&g_h[(size_t)(int)p3 * HID + j]);
        acc += v0 * __int_as_float((int)(p0 >> 32));
        acc += v1 * __int_as_float((int)(p1 >> 32));
        acc += v2 * __int_as_float((int)(p2 >> 32));
        acc += v3 * __int_as_float((int)(p3 >> 32));
    }
    for (; i < e; i++) {
        long long p0 = __ldg(&g_edge[i]);
        acc += __ldg(&g_h[(size_t)(int)p0 * HID + j]) *
               __int_as_float((int)(p0 >> 32));
    }
    g_aggh[(size_t)n * HID + j] = acc;
}

// Output GEMM, register-tiled: block (24,8); thread = 4 j-cols x 8 nodes.
// 64 nodes per block. sW = combined [96][96] (mu cols 0-47 | logstd 48-95).
#define ONPB 64
__global__ void k_out(const float* __restrict__ Wmu,
                      const float* __restrict__ bmu,
                      const float* __restrict__ Wls,
                      const float* __restrict__ bls,
                      float* __restrict__ out) {
    __shared__ __align__(16) float sW[HID * HID];     // 36864 B
    __shared__ float sh[ONPB * 97];                   // padded rows
    __shared__ float sb[HID];
    int tx = threadIdx.x, ty = threadIdx.y;
    int tid = ty * 24 + tx;                           // 0..191
    int base = blockIdx.x * ONPB;

    for (int t = tid; t < HID * HID; t += 192) {
        int c = t / HID, jj = t - c * HID;
        sW[t] = (jj < OUT_C) ? __ldg(&Wmu[c * OUT_C + jj])
                             : __ldg(&Wls[c * OUT_C + (jj - OUT_C)]);
    }
    if (tid < HID)
        sb[tid] = (tid < OUT_C) ? __ldg(&bmu[tid]) : __ldg(&bls[tid - OUT_C]);
    for (int t = tid; t < ONPB * HID; t += 192) {
        int nd = t / HID, c = t - nd * HID;
        int n = base + nd;
        sh[nd * 97 + c] = (n < N_NODES) ? g_aggh[(size_t)n * HID + c] : 0.0f;
    }
    __syncthreads();

    int j4 = tx * 4;
    float4 bias = *(const float4*)&sb[j4];
    float4 acc[8];
    #pragma unroll
    for (int k = 0; k < 8; k++) acc[k] = bias;

    #pragma unroll 2
    for (int c = 0; c < HID; c++) {
        float4 w = *(const float4*)&sW[c * HID + j4];
        #pragma unroll
        for (int k = 0; k < 8; k++) {
            float a = sh[(ty * 8 + k) * 97 + c];
            acc[k].x += a * w.x;
            acc[k].y += a * w.y;
            acc[k].z += a * w.z;
            acc[k].w += a * w.w;
        }
    }

    #pragma unroll
    for (int k = 0; k < 8; k++) {
        int n = base + ty * 8 + k;
        if (n >= N_NODES) continue;
        if (j4 < OUT_C)
            *(float4*)&out[(size_t)n * OUT_C + j4] = acc[k];
        else
            *(float4*)&out[(size_t)N_NODES * OUT_C + (size_t)n * OUT_C + (j4 - OUT_C)] = acc[k];
    }
}

extern "C" void kernel_launch(void* const* d_in, const int* in_sizes, int n_in,
                              void* d_out, int out_size) {
    const float* x   = (const float*)d_in[0];
    const int*   ei  = (const int*)d_in[1];
    const float* W1  = (const float*)d_in[2];
    const float* b1  = (const float*)d_in[3];
    const float* Wmu = (const float*)d_in[4];
    const float* bmu = (const float*)d_in[5];
    const float* Wls = (const float*)d_in[6];
    const float* bls = (const float*)d_in[7];
    float* out = (float*)d_out;

    k_zero_cnt<<<(N_NODES + 255) / 256, 256>>>();
    k_count<<<(E_EDGES + 255) / 256, 256>>>(ei);
    k_scan<<<1, 1024>>>();
    k_fill<<<(E_EDGES + 255) / 256, 256>>>(ei);
    k_fused1<<<(N_NODES + 3) / 4, dim3(96, 4)>>>(x, W1, b1);
    k_aggh_csr<<<(N_NODES + 3) / 4, dim3(HID, 4)>>>();
    k_out<<<(N_NODES + ONPB - 1) / ONPB, dim3(24, 8)>>>(Wmu, bmu, Wls, bls, out);
}

// round 6
// speedup vs baseline: 2.4687x; 1.4983x over previous
#include <cuda_runtime.h>
#include <cuda_bf16.h>
#include <stdint.h>

#define N_NODES 50000
#define E_EDGES 800000
#define IN_C    10
#define HID     96
#define OUT_C   48
#define SCAN_B  196          // ceil(50000/256)

// ---- scratch (device globals; no allocation allowed) ----
__device__ int       g_cnt[N_NODES];
__device__ int       g_bsum[256];           // per-block sums (padded)
__device__ int       g_boff[256];           // scanned block offsets
__device__ int       g_off[N_NODES + 1];
__device__ int       g_cur[N_NODES];
__device__ float     g_dis[N_NODES];
__device__ long long g_edge[E_EDGES];       // packed (w<<32 | src)
__device__ float     g_h   [N_NODES * HID];
__device__ float     g_aggh[N_NODES * HID];

__global__ void k_zero_cnt() {
    int n = blockIdx.x * blockDim.x + threadIdx.x;
    if (n < N_NODES) g_cnt[n] = 0;
}

// 2 edges per thread (int2)
__global__ void k_count(const int* __restrict__ ei) {
    int t = blockIdx.x * blockDim.x + threadIdx.x;
    if (t * 2 >= E_EDGES) return;
    int2 c2 = __ldg((const int2*)(ei + E_EDGES) + t);
    atomicAdd(&g_cnt[c2.x], 1);
    atomicAdd(&g_cnt[c2.y], 1);
}

// level-1: per-block (256-wide) sums of cnt
__global__ void k_blocksum() {
    __shared__ int wsum[8];
    int idx = blockIdx.x * 256 + threadIdx.x;
    int v = (idx < N_NODES) ? g_cnt[idx] : 0;
    int s = v;
    #pragma unroll
    for (int o = 16; o > 0; o >>= 1) s += __shfl_down_sync(0xffffffffu, s, o);
    if ((threadIdx.x & 31) == 0) wsum[threadIdx.x >> 5] = s;
    __syncthreads();
    if (threadIdx.x < 8) {
        int t = wsum[threadIdx.x];
        #pragma unroll
        for (int o = 4; o > 0; o >>= 1) t += __shfl_down_sync(0xffu, t, o);
        if (threadIdx.x == 0) g_bsum[blockIdx.x] = t;
    }
}

// level-2: exclusive scan of 196 block sums (one tiny block)
__global__ void k_scanmid() {
    __shared__ int ws[8];
    int t = threadIdx.x;                          // 0..255
    int v = (t < SCAN_B) ? g_bsum[t] : 0;
    int inc = v;
    #pragma unroll
    for (int o = 1; o < 32; o <<= 1) {
        int u = __shfl_up_sync(0xffffffffu, inc, o);
        if ((t & 31) >= o) inc += u;
    }
    if ((t & 31) == 31) ws[t >> 5] = inc;
    __syncthreads();
    if (t < 8) {
        int wv = ws[t];
        int winc = wv;
        #pragma unroll
        for (int o = 1; o < 8; o <<= 1) {
            int u = __shfl_up_sync(0xffu, winc, o);
            if (t >= o) winc += u;
        }
        ws[t] = winc - wv;                        // exclusive warp offset
    }
    __syncthreads();
    if (t < SCAN_B) g_boff[t] = inc - v + ws[t >> 5];
    if (t == 0) g_off[N_NODES] = E_EDGES;
}

// level-3: block-local exclusive scan + apply; writes off, cur, dis
__global__ void k_apply() {
    __shared__ int ws[8];
    int idx = blockIdx.x * 256 + threadIdx.x;
    int t = threadIdx.x;
    int v = (idx < N_NODES) ? g_cnt[idx] : 0;
    int inc = v;
    #pragma unroll
    for (int o = 1; o < 32; o <<= 1) {
        int u = __shfl_up_sync(0xffffffffu, inc, o);
        if ((t & 31) >= o) inc += u;
    }
    if ((t & 31) == 31) ws[t >> 5] = inc;
    __syncthreads();
    if (t < 8) {
        int wv = ws[t];
        int winc = wv;
        #pragma unroll
        for (int o = 1; o < 8; o <<= 1) {
            int u = __shfl_up_sync(0xffu, winc, o);
            if (t >= o) winc += u;
        }
        ws[t] = winc - wv;
    }
    __syncthreads();
    if (idx < N_NODES) {
        int off = g_boff[blockIdx.x] + ws[t >> 5] + (inc - v);
        g_off[idx] = off;
        g_cur[idx] = off;
        g_dis[idx] = rsqrtf((float)(v + 1));
    }
}

__global__ void k_fill(const int* __restrict__ ei) {
    int e = blockIdx.x * blockDim.x + threadIdx.x;
    if (e >= E_EDGES) return;
    int row = __ldg(&ei[e]);
    int col = __ldg(&ei[E_EDGES + e]);
    float w = __ldg(&g_dis[row]) * __ldg(&g_dis[col]);
    int pos = atomicAdd(&g_cur[col], 1);
    g_edge[pos] = ((long long)__float_as_int(w) << 32) | (unsigned int)row;
}

// Fused: agg_x (CSR gather, 10-wide) + layer1 projection + relu.
__global__ void k_fused1(const float* __restrict__ x,
                         const float* __restrict__ W1,
                         const float* __restrict__ b1) {
    __shared__ float part[4][9][10];
    __shared__ float sagg[4][10];
    __shared__ float sW1[IN_C * HID];
    __shared__ float sb1[HID];
    int tx = threadIdx.x, ty = threadIdx.y;
    int tid = ty * 96 + tx;
    for (int t = tid; t < IN_C * HID; t += 384) sW1[t] = W1[t];
    if (tid < HID) sb1[tid] = b1[tid];
    int n = blockIdx.x * 4 + ty;

    int g = tx / 10;
    int c = tx - g * 10;
    if (tx < 90 && n < N_NODES) {
        float p = 0.0f;
        int s = g_off[n], e = g_off[n + 1];
        for (int i = s + g; i < e; i += 9) {
            long long pk = __ldg(&g_edge[i]);
            p += __ldg(&x[(size_t)(int)pk * IN_C + c]) *
                 __int_as_float((int)(pk >> 32));
        }
        part[ty][g][c] = p;
    }
    __syncthreads();
    if (tx < IN_C && n < N_NODES) {
        float d = g_dis[n];
        float a = __ldg(&x[(size_t)n * IN_C + tx]) * d * d;
        #pragma unroll
        for (int g2 = 0; g2 < 9; g2++) a += part[ty][g2][tx];
        sagg[ty][tx] = a;
    }
    __syncthreads();
    if (n >= N_NODES) return;
    float acc = sb1[tx];
    #pragma unroll
    for (int cc = 0; cc < IN_C; cc++)
        acc += sagg[ty][cc] * sW1[cc * HID + tx];
    g_h[(size_t)n * HID + tx] = fmaxf(acc, 0.0f);
}

// agg_h[n][j] = h[n][j]*dis[n]^2 + sum_e h[src][j]*w  (96-wide, unroll 4)
__global__ void k_aggh_csr() {
    int n = blockIdx.x * 4 + threadIdx.y;
    if (n >= N_NODES) return;
    int j = threadIdx.x;
    float d = g_dis[n];
    float acc = g_h[(size_t)n * HID + j] * d * d;
    int s = g_off[n], e = g_off[n + 1];
    int cnt4 = (e - s) & ~3;
    int i = s;
    for (; i < s + cnt4; i += 4) {
        long long p0 = __ldg(&g_edge[i]);
        long long p1 = __ldg(&g_edge[i + 1]);
        long long p2 = __ldg(&g_edge[i + 2]);
        long long p3 = __ldg(&g_edge[i + 3]);
        float v0 = __ldg(&g_h[(size_t)(int)p0 * HID + j]);
        float v1 = __ldg(&g_h[(size_t)(int)p1 * HID + j]);
        float v2 = __ldg(&g_h[(size_t)(int)p2 * HID + j]);
        float v3 = __ldg(&g_h[(size_t)(int)p3 * HID + j]);
        acc += v0 * __int_as_float((int)(p0 >> 32));
        acc += v1 * __int_as_float((int)(p1 >> 32));
        acc += v2 * __int_as_float((int)(p2 >> 32));
        acc += v3 * __int_as_float((int)(p3 >> 32));
    }
    for (; i < e; i++) {
        long long p0 = __ldg(&g_edge[i]);
        acc += __ldg(&g_h[(size_t)(int)p0 * HID + j]) *
               __int_as_float((int)(p0 >> 32));
    }
    g_aggh[(size_t)n * HID + j] = acc;
}

// Output GEMM: block (12,8) = 96 thr; thread = 8 j-cols x 8 nodes; 64 nodes/blk.
// W staged in 4 chunks of 24 rows (smem 34KB/block).
#define ONPB 64
__global__ void k_out(const float* __restrict__ Wmu,
                      const float* __restrict__ bmu,
                      const float* __restrict__ Wls,
                      const float* __restrict__ bls,
                      float* __restrict__ out) {
    __shared__ __align__(16) float sW[24 * HID];      // 9216 B chunk
    __shared__ float sh[ONPB * 97];                   // 24832 B
    __shared__ float sb[HID];
    int tx = threadIdx.x, ty = threadIdx.y;
    int tid = ty * 12 + tx;                           // 0..95
    int base = blockIdx.x * ONPB;

    if (tid < HID)
        sb[tid] = (tid < OUT_C) ? __ldg(&bmu[tid]) : __ldg(&bls[tid - OUT_C]);
    // stage agg rows (vector loads, padded scalar stores)
    for (int t = tid; t < ONPB * 24; t += 96) {
        int nd = t / 24, c4 = (t - nd * 24) * 4;
        int n = base + nd;
        float4 v = (n < N_NODES) ? __ldg((const float4*)&g_aggh[(size_t)n * HID + c4])
                                 : make_float4(0.f, 0.f, 0.f, 0.f);
        float* dst = &sh[nd * 97 + c4];
        dst[0] = v.x; dst[1] = v.y; dst[2] = v.z; dst[3] = v.w;
    }

    int j8 = tx * 8;
    float4 acc0[8], acc1[8];
    {
        // bias (sb not yet guaranteed visible; sync first)
        __syncthreads();
        float4 b0 = *(const float4*)&sb[j8];
        float4 b1v = *(const float4*)&sb[j8 + 4];
        #pragma unroll
        for (int k = 0; k < 8; k++) { acc0[k] = b0; acc1[k] = b1v; }
    }

    #pragma unroll
    for (int cb = 0; cb < 4; cb++) {
        // load W chunk rows [cb*24, cb*24+24)
        for (int t = tid; t < 24 * 24; t += 96) {    // 576 float4
            int r = t / 24, q4 = (t - r * 24) * 4;
            int c = cb * 24 + r;
            float4 w;
            if (q4 < OUT_C && q4 + 3 < OUT_C) {
                w = __ldg((const float4*)&Wmu[c * OUT_C + q4]);
            } else {
                w = __ldg((const float4*)&Wls[c * OUT_C + (q4 - OUT_C)]);
            }
            *(float4*)&sW[r * HID + q4] = w;
        }
        __syncthreads();
        #pragma unroll 4
        for (int c = 0; c < 24; c++) {
            float4 w0 = *(const float4*)&sW[c * HID + j8];
            float4 w1 = *(const float4*)&sW[c * HID + j8 + 4];
            #pragma unroll
            for (int k = 0; k < 8; k++) {
                float a = sh[(ty * 8 + k) * 97 + cb * 24 + c];
                acc0[k].x += a * w0.x; acc0[k].y += a * w0.y;
                acc0[k].z += a * w0.z; acc0[k].w += a * w0.w;
                acc1[k].x += a * w1.x; acc1[k].y += a * w1.y;
                acc1[k].z += a * w1.z; acc1[k].w += a * w1.w;
            }
        }
        __syncthreads();
    }

    #pragma unroll
    for (int k = 0; k < 8; k++) {
        int n = base + ty * 8 + k;
        if (n >= N_NODES) continue;
        if (j8 < OUT_C) {
            *(float4*)&out[(size_t)n * OUT_C + j8] = acc0[k];
            *(float4*)&out[(size_t)n * OUT_C + j8 + 4] = acc1[k];
        } else {
            size_t o = (size_t)N_NODES * OUT_C + (size_t)n * OUT_C + (j8 - OUT_C);
            *(float4*)&out[o] = acc0[k];
            *(float4*)&out[o + 4] = acc1[k];
        }
    }
}

extern "C" void kernel_launch(void* const* d_in, const int* in_sizes, int n_in,
                              void* d_out, int out_size) {
    const float* x   = (const float*)d_in[0];
    const int*   ei  = (const int*)d_in[1];
    const float* W1  = (const float*)d_in[2];
    const float* b1  = (const float*)d_in[3];
    const float* Wmu = (const float*)d_in[4];
    const float* bmu = (const float*)d_in[5];
    const float* Wls = (const float*)d_in[6];
    const float* bls = (const float*)d_in[7];
    float* out = (float*)d_out;

    k_zero_cnt<<<(N_NODES + 255) / 256, 256>>>();
    k_count<<<(E_EDGES / 2 + 255) / 256, 256>>>(ei);
    k_blocksum<<<SCAN_B, 256>>>();
    k_scanmid<<<1, 256>>>();
    k_apply<<<SCAN_B, 256>>>();
    k_fill<<<(E_EDGES + 255) / 256, 256>>>(ei);
    k_fused1<<<(N_NODES + 3) / 4, dim3(96, 4)>>>(x, W1, b1);
    k_aggh_csr<<<(N_NODES + 3) / 4, dim3(HID, 4)>>>();
    k_out<<<(N_NODES + ONPB - 1) / ONPB, dim3(12, 8)>>>(Wmu, bmu, Wls, bls, out);
}